// round 11
// baseline (speedup 1.0000x reference)
#include <cuda_runtime.h>
#include <math.h>
#include <stdint.h>

// ---------------- problem constants ----------------
#define T_TOK 4096
#define H_DIM 2048
#define E_EXP 32
#define NE    48
#define I_DIM 1024
#define TOPK  6
#define ROUTED_SCALE 2.5f
#define CAP   4096

// ---------------- device scratch (static, no allocs) ----------------
__device__ int   g_count[E_EXP];
__device__ int   g_tok[E_EXP * CAP];
__device__ int   g_nk[T_TOK];
__device__ int   g_slots[T_TOK * TOPK];
__device__ float g_wts[T_TOK * TOPK];
__device__ float g_zero_w[T_TOK];
__device__ float g_xtf[(size_t)T_TOK * H_DIM];          // x pre-rounded to tf32
__device__ float g_act[(size_t)E_EXP * CAP * I_DIM];    // stored tf32-rounded
__device__ float g_y[(size_t)E_EXP * CAP * H_DIM];

// ---------------- kernel 0 ----------------
__global__ void zero_counts_kernel() {
    int i = threadIdx.x;
    if (i < E_EXP) g_count[i] = 0;
}

// ---------------- helpers ----------------
__device__ __forceinline__ uint32_t f2tf_bits(uint32_t bits) {
    uint32_t r;
    asm("cvt.rna.tf32.f32 %0, %1;" : "=r"(r) : "r"(bits));
    return r;
}
__device__ __forceinline__ float f2tf_f(float f) {
    uint32_t r;
    asm("cvt.rna.tf32.f32 %0, %1;" : "=r"(r) : "f"(f));
    return __uint_as_float(r);
}

// ---------------- kernel 0b: pre-round x to tf32 ----------------
__global__ __launch_bounds__(256)
void round_x_kernel(const float* __restrict__ x) {
    size_t i = ((size_t)blockIdx.x * 256 + threadIdx.x) * 4;
    if (i < (size_t)T_TOK * H_DIM) {
        float4 v = *(const float4*)(x + i);
        v.x = f2tf_f(v.x); v.y = f2tf_f(v.y); v.z = f2tf_f(v.z); v.w = f2tf_f(v.w);
        *(float4*)(g_xtf + i) = v;
    }
}

// ---------------- kernel 1: router (exact fp32 — selection must not flip) ----------------
__global__ __launch_bounds__(256)
void router_kernel(const float* __restrict__ x,
                   const float* __restrict__ rw,
                   const float* __restrict__ bias) {
    int t   = blockIdx.x;
    int tid = threadIdx.x;
    __shared__ float sx[H_DIM];
    __shared__ float slog[NE];

    const float* xrow = x + (size_t)t * H_DIM;
    for (int i = tid; i < H_DIM; i += 256) sx[i] = xrow[i];
    __syncthreads();

    int warp = tid >> 5, lane = tid & 31;
    for (int e = warp; e < NE; e += 8) {
        const float* w = rw + (size_t)e * H_DIM;
        float acc = 0.f;
        for (int i = lane; i < H_DIM; i += 32) acc += sx[i] * w[i];
        #pragma unroll
        for (int o = 16; o; o >>= 1) acc += __shfl_xor_sync(0xffffffffu, acc, o);
        if (lane == 0) slog[e] = acc;
    }
    __syncthreads();

    if (tid == 0) {
        float sc[NE], scc[NE];
        #pragma unroll
        for (int e = 0; e < NE; e++) {
            float s = 1.f / (1.f + expf(-slog[e]));
            sc[e]  = s;
            scc[e] = s + bias[e];
        }
        int ids[TOPK]; float wts[TOPK]; float sum = 0.f;
        bool used[NE];
        #pragma unroll
        for (int e = 0; e < NE; e++) used[e] = false;
        #pragma unroll
        for (int k = 0; k < TOPK; k++) {
            int bi = 0; float bv = -1e30f;
            for (int e = 0; e < NE; e++)
                if (!used[e] && scc[e] > bv) { bv = scc[e]; bi = e; }  // strict > : lowest idx on tie
            used[bi] = true; ids[k] = bi; wts[k] = sc[bi]; sum += sc[bi];
        }
        float inv = ROUTED_SCALE / sum;
        float zw = 0.f;
        int nk = 0;
        #pragma unroll
        for (int k = 0; k < TOPK; k++) {
            float w = wts[k] * inv;
            if (ids[k] >= E_EXP) {
                zw += w;
            } else {
                int e = ids[k];
                int pos = atomicAdd(&g_count[e], 1);
                g_tok[e * CAP + pos] = t;
                g_slots[t * TOPK + nk] = e * CAP + pos;
                g_wts[t * TOPK + nk] = w;
                nk++;
            }
        }
        g_nk[t] = nk;
        g_zero_w[t] = zw;
    }
}

// ---------------- mma + cp.async helpers ----------------
__device__ __forceinline__ void mma_tf32(float* d, const uint32_t* a, const uint32_t* b) {
    asm volatile(
        "mma.sync.aligned.m16n8k8.row.col.f32.tf32.tf32.f32 "
        "{%0,%1,%2,%3}, {%4,%5,%6,%7}, {%8,%9}, {%0,%1,%2,%3};\n"
        : "+f"(d[0]), "+f"(d[1]), "+f"(d[2]), "+f"(d[3])
        : "r"(a[0]), "r"(a[1]), "r"(a[2]), "r"(a[3]),
          "r"(b[0]), "r"(b[1]));
}
__device__ __forceinline__ uint32_t smem_u32(const void* p) {
    uint32_t a;
    asm("{ .reg .u64 t; cvta.to.shared.u64 t, %1; cvt.u32.u64 %0, t; }"
        : "=r"(a) : "l"(p));
    return a;
}
__device__ __forceinline__ void cp16(uint32_t d, const void* s) {
    asm volatile("cp.async.cg.shared.global [%0], [%1], 16;" :: "r"(d), "l"(s));
}
__device__ __forceinline__ void cp_commit() { asm volatile("cp.async.commit_group;" ::: "memory"); }
__device__ __forceinline__ void cp_wait0()  { asm volatile("cp.async.wait_group 0;" ::: "memory"); }

// ---------------- GEMM tiling ----------------
#define BM 128
#define BN 128
#define BK 32
#define SPAD 36                    // bank(36g+tg)=(4g+tg)%32 all-distinct -> conflict-free
#define ABUF (BM * SPAD)           // words
#define BBUF (BN * SPAD)
#define STW  (ABUF + BBUF)         // words per stage = 9216
#define STAGES 2
#define SMEM_BYTES (STAGES * STW * 4)   // 73728 B -> 2 CTAs/SM fits (147KB < 228KB)

// Core pipelined tile compute: 8 warps (2x4), 64x32 warp tiles, 256 threads.
// BK=32: 4 unrolled k8 iterations per chunk; half the barrier count of BK=16.
// A source is PRE-ROUNDED tf32 (no cvt); B (weights) cvt'd at the fragment.
// 2-stage double buffer: wait_group 0 at top (only group(c) outstanding);
// the same barrier orders compute(c-1) before the overwrite of stage (c+1)&1.
template<int NKT>
__device__ __forceinline__ void gemm_tile(uint32_t sb,
                                          const float* aptr,   // row base + half offset
                                          const float* bptr,   // row base + half offset
                                          float acc[4][4][4],
                                          int wm, int wn, int g, int tg,
                                          int tid) {
    uint32_t adst = sb + (uint32_t)((tid >> 1) * SPAD + (tid & 1) * 16) * 4;
    uint32_t bdst = sb + (uint32_t)(ABUF + (tid >> 1) * SPAD + (tid & 1) * 16) * 4;

    // prologue: chunk 0 into stage 0
    #pragma unroll
    for (int j = 0; j < 4; j++) {
        cp16(adst + j * 16, aptr + j * 4);
        cp16(bdst + j * 16, bptr + j * 4);
    }
    cp_commit();

    #pragma unroll 1
    for (int c = 0; c < NKT; c++) {
        int st = c & 1;
        cp_wait0();            // only group(c) outstanding here
        __syncthreads();       // + orders compute(c-1) before overwrite below

        if (c + 1 < NKT) {
            uint32_t stoff = (uint32_t)((st ^ 1) * STW) * 4;
            int k0 = (c + 1) * BK;
            #pragma unroll
            for (int j = 0; j < 4; j++) {
                cp16(adst + stoff + j * 16, aptr + k0 + j * 4);
                cp16(bdst + stoff + j * 16, bptr + k0 + j * 4);
            }
            cp_commit();
        }

        {
            uint32_t abase = sb + (uint32_t)(st * STW) * 4;
            uint32_t bbase = abase + (uint32_t)ABUF * 4;
            #pragma unroll
            for (int k8 = 0; k8 < BK; k8 += 8) {
                uint32_t afr[4][4], bfr[4][2];
                #pragma unroll
                for (int mt = 0; mt < 4; mt++) {
                    int r0 = wm * 64 + mt * 16;
                    uint32_t p0 = abase + ((r0 + g) * SPAD + k8 + tg) * 4;
                    uint32_t p1 = abase + ((r0 + g + 8) * SPAD + k8 + tg) * 4;
                    asm volatile("ld.shared.b32 %0, [%1];" : "=r"(afr[mt][0]) : "r"(p0));
                    asm volatile("ld.shared.b32 %0, [%1];" : "=r"(afr[mt][1]) : "r"(p1));
                    asm volatile("ld.shared.b32 %0, [%1];" : "=r"(afr[mt][2]) : "r"(p0 + 16));
                    asm volatile("ld.shared.b32 %0, [%1];" : "=r"(afr[mt][3]) : "r"(p1 + 16));
                }
                #pragma unroll
                for (int nt = 0; nt < 4; nt++) {
                    int c0 = wn * 32 + nt * 8 + g;
                    uint32_t p = bbase + (c0 * SPAD + k8 + tg) * 4;
                    asm volatile("ld.shared.b32 %0, [%1];" : "=r"(bfr[nt][0]) : "r"(p));
                    asm volatile("ld.shared.b32 %0, [%1];" : "=r"(bfr[nt][1]) : "r"(p + 16));
                    bfr[nt][0] = f2tf_bits(bfr[nt][0]);
                    bfr[nt][1] = f2tf_bits(bfr[nt][1]);
                }
                #pragma unroll
                for (int mt = 0; mt < 4; mt++)
                    #pragma unroll
                    for (int nt = 0; nt < 4; nt++)
                        mma_tf32(acc[mt][nt], afr[mt], bfr[nt]);
            }
        }
    }
    __syncthreads();
}

// kernel 2: act = silu(x@w1^T)*(x@w3^T); B rows interleaved w1/w3 (64 features/block)
__global__ __launch_bounds__(256, 2)
void gemm1_kernel(const float* __restrict__ w1,
                  const float* __restrict__ w3) {
    int e   = blockIdx.z;
    int cnt = g_count[e];
    int m0  = blockIdx.y * BM;
    if (m0 >= cnt) return;
    int f0  = blockIdx.x * (BN / 2);

    extern __shared__ __align__(16) uint32_t smw[];
    uint32_t sb = smem_u32(smw);
    int tid = threadIdx.x, warp = tid >> 5, lane = tid & 31;
    int wm = warp >> 2, wn = warp & 3;     // 2x4 warp grid, 64x32 warp tiles
    int g = lane >> 2, tg = lane & 3;

    int r = tid >> 1, half = (tid & 1) * 16;
    int arow = m0 + r; if (arow >= cnt) arow = cnt - 1;
    int tok = g_tok[e * CAP + arow];
    const float* aptr = g_xtf + (size_t)tok * H_DIM + half;
    const float* bptr = ((r & 1) ? w3 : w1)
                      + ((size_t)e * I_DIM + f0 + (r >> 1)) * H_DIM + half;

    float acc[4][4][4];
    #pragma unroll
    for (int mt = 0; mt < 4; mt++)
        #pragma unroll
        for (int nt = 0; nt < 4; nt++)
            #pragma unroll
            for (int i = 0; i < 4; i++) acc[mt][nt][i] = 0.f;

    gemm_tile<H_DIM / BK>(sb, aptr, bptr, acc, wm, wn, g, tg, tid);

    // epilogue: col 2j=gate, 2j+1=up -> silu(gate)*up, stored tf32-rounded
    #pragma unroll
    for (int mt = 0; mt < 4; mt++) {
        int row = m0 + wm * 64 + mt * 16 + g;
        #pragma unroll
        for (int nt = 0; nt < 4; nt++) {
            int f = f0 + wn * 16 + nt * 4 + tg;
            float* d = acc[mt][nt];
            if (row < cnt) {
                float gt = d[0], up = d[1];
                g_act[((size_t)e * CAP + row) * I_DIM + f] =
                    f2tf_f(gt / (1.f + expf(-gt)) * up);
            }
            if (row + 8 < cnt) {
                float gt = d[2], up = d[3];
                g_act[((size_t)e * CAP + row + 8) * I_DIM + f] =
                    f2tf_f(gt / (1.f + expf(-gt)) * up);
            }
        }
    }
}

// kernel 3: y = act @ w2^T (per-slot output, deterministic)
__global__ __launch_bounds__(256, 2)
void gemm2_kernel(const float* __restrict__ w2) {
    int e   = blockIdx.z;
    int cnt = g_count[e];
    int m0  = blockIdx.y * BM;
    if (m0 >= cnt) return;
    int n0  = blockIdx.x * BN;

    extern __shared__ __align__(16) uint32_t smw[];
    uint32_t sb = smem_u32(smw);
    int tid = threadIdx.x, warp = tid >> 5, lane = tid & 31;
    int wm = warp >> 2, wn = warp & 3;
    int g = lane >> 2, tg = lane & 3;

    int r = tid >> 1, half = (tid & 1) * 16;
    int arow = m0 + r; if (arow >= cnt) arow = cnt - 1;
    const float* aptr = g_act + ((size_t)e * CAP + arow) * I_DIM + half;
    const float* bptr = w2 + ((size_t)e * H_DIM + n0 + r) * I_DIM + half;

    float acc[4][4][4];
    #pragma unroll
    for (int mt = 0; mt < 4; mt++)
        #pragma unroll
        for (int nt = 0; nt < 4; nt++)
            #pragma unroll
            for (int i = 0; i < 4; i++) acc[mt][nt][i] = 0.f;

    gemm_tile<I_DIM / BK>(sb, aptr, bptr, acc, wm, wn, g, tg, tid);

    #pragma unroll
    for (int mt = 0; mt < 4; mt++) {
        int row = m0 + wm * 64 + mt * 16 + g;
        #pragma unroll
        for (int nt = 0; nt < 4; nt++) {
            int col = n0 + wn * 32 + nt * 8 + 2 * tg;
            float* d = acc[mt][nt];
            if (row < cnt)
                *(float2*)&g_y[((size_t)e * CAP + row) * H_DIM + col]
                    = make_float2(d[0], d[1]);
            if (row + 8 < cnt)
                *(float2*)&g_y[((size_t)e * CAP + row + 8) * H_DIM + col]
                    = make_float2(d[2], d[3]);
        }
    }
}

// ---------------- kernel 4: combine ----------------
__global__ __launch_bounds__(256)
void combine_kernel(const float* __restrict__ x, float* __restrict__ out) {
    int t = blockIdx.x;
    __shared__ int   s_n;
    __shared__ float s_zw;
    __shared__ int   s_slot[TOPK];
    __shared__ float s_w[TOPK];
    int tid = threadIdx.x;
    if (tid == 0) { s_n = g_nk[t]; s_zw = g_zero_w[t]; }
    if (tid < TOPK) { s_slot[tid] = g_slots[t * TOPK + tid]; s_w[tid] = g_wts[t * TOPK + tid]; }
    __syncthreads();
    int n = s_n; float zw = s_zw;

    const float* xrow = x + (size_t)t * H_DIM;
    float* orow = out + (size_t)t * H_DIM;
    for (int h = tid * 4; h < H_DIM; h += 256 * 4) {
        float4 xv = *(const float4*)(xrow + h);
        float4 o = make_float4(xv.x * zw, xv.y * zw, xv.z * zw, xv.w * zw);
        for (int k = 0; k < n; k++) {
            const float4 yv = *(const float4*)(g_y + (size_t)s_slot[k] * H_DIM + h);
            float wk = s_w[k];
            o.x += wk * yv.x; o.y += wk * yv.y; o.z += wk * yv.z; o.w += wk * yv.w;
        }
        *(float4*)(orow + h) = o;
    }
}

// ---------------- launcher ----------------
extern "C" void kernel_launch(void* const* d_in, const int* in_sizes, int n_in,
                              void* d_out, int out_size) {
    const float* x    = (const float*)d_in[0];
    const float* rw   = (const float*)d_in[1];
    const float* bias = (const float*)d_in[2];
    const float* w1   = (const float*)d_in[3];
    const float* w3   = (const float*)d_in[4];
    const float* w2   = (const float*)d_in[5];
    float* out = (float*)d_out;

    cudaFuncSetAttribute(gemm1_kernel, cudaFuncAttributeMaxDynamicSharedMemorySize, SMEM_BYTES);
    cudaFuncSetAttribute(gemm2_kernel, cudaFuncAttributeMaxDynamicSharedMemorySize, SMEM_BYTES);

    zero_counts_kernel<<<1, 32>>>();
    round_x_kernel<<<(T_TOK * H_DIM / 4 + 255) / 256, 256>>>(x);
    router_kernel<<<T_TOK, 256>>>(x, rw, bias);
    {
        dim3 g((2 * I_DIM) / BN, T_TOK / BM, E_EXP);  // 16 x 32 x 32
        gemm1_kernel<<<g, 256, SMEM_BYTES>>>(w1, w3);
    }
    {
        dim3 g(H_DIM / BN, T_TOK / BM, E_EXP);        // 16 x 32 x 32
        gemm2_kernel<<<g, 256, SMEM_BYTES>>>(w2);
    }
    combine_kernel<<<T_TOK, 256>>>(x, out);
}

// round 12
// speedup vs baseline: 1.0203x; 1.0203x over previous
#include <cuda_runtime.h>
#include <math.h>
#include <stdint.h>

// ---------------- problem constants ----------------
#define T_TOK 4096
#define H_DIM 2048
#define E_EXP 32
#define NE    48
#define I_DIM 1024
#define TOPK  6
#define ROUTED_SCALE 2.5f
#define CAP   4096

// ---------------- device scratch (static, no allocs) ----------------
__device__ int   g_count[E_EXP];
__device__ int   g_tok[E_EXP * CAP];
__device__ int   g_nk[T_TOK];
__device__ int   g_slots[T_TOK * TOPK];
__device__ float g_wts[T_TOK * TOPK];
__device__ float g_zero_w[T_TOK];
__device__ float g_xtf[(size_t)T_TOK * H_DIM];          // x pre-rounded to tf32
__device__ float g_act[(size_t)E_EXP * CAP * I_DIM];    // stored tf32-rounded
__device__ float g_y[(size_t)E_EXP * CAP * H_DIM];

// ---------------- kernel 0 ----------------
__global__ void zero_counts_kernel() {
    int i = threadIdx.x;
    if (i < E_EXP) g_count[i] = 0;
}

// ---------------- helpers ----------------
__device__ __forceinline__ uint32_t f2tf_bits(uint32_t bits) {
    uint32_t r;
    asm("cvt.rna.tf32.f32 %0, %1;" : "=r"(r) : "r"(bits));
    return r;
}
__device__ __forceinline__ float f2tf_f(float f) {
    uint32_t r;
    asm("cvt.rna.tf32.f32 %0, %1;" : "=r"(r) : "f"(f));
    return __uint_as_float(r);
}

// ---------------- kernel 0b: pre-round x to tf32 ----------------
__global__ __launch_bounds__(256)
void round_x_kernel(const float* __restrict__ x) {
    size_t i = ((size_t)blockIdx.x * 256 + threadIdx.x) * 4;
    if (i < (size_t)T_TOK * H_DIM) {
        float4 v = *(const float4*)(x + i);
        v.x = f2tf_f(v.x); v.y = f2tf_f(v.y); v.z = f2tf_f(v.z); v.w = f2tf_f(v.w);
        *(float4*)(g_xtf + i) = v;
    }
}

// ---------------- kernel 1: router (exact fp32 — selection must not flip) ----------------
__global__ __launch_bounds__(256)
void router_kernel(const float* __restrict__ x,
                   const float* __restrict__ rw,
                   const float* __restrict__ bias) {
    int t   = blockIdx.x;
    int tid = threadIdx.x;
    __shared__ float sx[H_DIM];
    __shared__ float slog[NE];

    const float* xrow = x + (size_t)t * H_DIM;
    for (int i = tid; i < H_DIM; i += 256) sx[i] = xrow[i];
    __syncthreads();

    int warp = tid >> 5, lane = tid & 31;
    for (int e = warp; e < NE; e += 8) {
        const float* w = rw + (size_t)e * H_DIM;
        float acc = 0.f;
        for (int i = lane; i < H_DIM; i += 32) acc += sx[i] * w[i];
        #pragma unroll
        for (int o = 16; o; o >>= 1) acc += __shfl_xor_sync(0xffffffffu, acc, o);
        if (lane == 0) slog[e] = acc;
    }
    __syncthreads();

    if (tid == 0) {
        float sc[NE], scc[NE];
        #pragma unroll
        for (int e = 0; e < NE; e++) {
            float s = 1.f / (1.f + expf(-slog[e]));
            sc[e]  = s;
            scc[e] = s + bias[e];
        }
        int ids[TOPK]; float wts[TOPK]; float sum = 0.f;
        bool used[NE];
        #pragma unroll
        for (int e = 0; e < NE; e++) used[e] = false;
        #pragma unroll
        for (int k = 0; k < TOPK; k++) {
            int bi = 0; float bv = -1e30f;
            for (int e = 0; e < NE; e++)
                if (!used[e] && scc[e] > bv) { bv = scc[e]; bi = e; }  // strict > : lowest idx on tie
            used[bi] = true; ids[k] = bi; wts[k] = sc[bi]; sum += sc[bi];
        }
        float inv = ROUTED_SCALE / sum;
        float zw = 0.f;
        int nk = 0;
        #pragma unroll
        for (int k = 0; k < TOPK; k++) {
            float w = wts[k] * inv;
            if (ids[k] >= E_EXP) {
                zw += w;
            } else {
                int e = ids[k];
                int pos = atomicAdd(&g_count[e], 1);
                g_tok[e * CAP + pos] = t;
                g_slots[t * TOPK + nk] = e * CAP + pos;
                g_wts[t * TOPK + nk] = w;
                nk++;
            }
        }
        g_nk[t] = nk;
        g_zero_w[t] = zw;
    }
}

// ---------------- mma + cp.async helpers ----------------
__device__ __forceinline__ void mma_tf32(float* d, const uint32_t* a, const uint32_t* b) {
    asm volatile(
        "mma.sync.aligned.m16n8k8.row.col.f32.tf32.tf32.f32 "
        "{%0,%1,%2,%3}, {%4,%5,%6,%7}, {%8,%9}, {%0,%1,%2,%3};\n"
        : "+f"(d[0]), "+f"(d[1]), "+f"(d[2]), "+f"(d[3])
        : "r"(a[0]), "r"(a[1]), "r"(a[2]), "r"(a[3]),
          "r"(b[0]), "r"(b[1]));
}
__device__ __forceinline__ uint32_t smem_u32(const void* p) {
    uint32_t a;
    asm("{ .reg .u64 t; cvta.to.shared.u64 t, %1; cvt.u32.u64 %0, t; }"
        : "=r"(a) : "l"(p));
    return a;
}
__device__ __forceinline__ void cp16(uint32_t d, const void* s) {
    asm volatile("cp.async.cg.shared.global [%0], [%1], 16;" :: "r"(d), "l"(s));
}
__device__ __forceinline__ void cp_commit() { asm volatile("cp.async.commit_group;" ::: "memory"); }
__device__ __forceinline__ void cp_wait1()  { asm volatile("cp.async.wait_group 1;" ::: "memory"); }

// ---------------- GEMM tiling ----------------
#define BM 128
#define BN 128
#define BK 32
#define SPAD 36                    // bank(36g+tg)=(4g+tg)%32 all-distinct -> conflict-free
#define ABUF (BM * SPAD)           // words
#define BBUF (BN * SPAD)
#define STW  (ABUF + BBUF)         // words per stage = 9216
#define STAGES 3
#define SMEM_BYTES (STAGES * STW * 4)   // 110592 B -> 2 CTAs/SM = 221KB <= 228KB

// Core pipelined tile compute: 8 warps (2x4), 64x32 warp tiles, 256 threads.
// BK=32 (4 unrolled k8 per chunk, half the sync points of BK=16) combined with
// the R9 pipeline: 3 stages, prefetch distance 2, wait_group<=1 at the top.
// A source is PRE-ROUNDED tf32 (no cvt); B (weights) cvt'd at the fragment.
template<int NKT>
__device__ __forceinline__ void gemm_tile(uint32_t sb,
                                          const float* aptr,   // row base + half offset
                                          const float* bptr,   // row base + half offset
                                          float acc[4][4][4],
                                          int wm, int wn, int g, int tg,
                                          int tid) {
    uint32_t adst = sb + (uint32_t)((tid >> 1) * SPAD + (tid & 1) * 16) * 4;
    uint32_t bdst = sb + (uint32_t)(ABUF + (tid >> 1) * SPAD + (tid & 1) * 16) * 4;

    // prologue: chunks 0,1 into stages 0,1
    #pragma unroll
    for (int s = 0; s < 2; s++) {
        uint32_t st = (uint32_t)(s * STW) * 4;
        #pragma unroll
        for (int j = 0; j < 4; j++) {
            cp16(adst + st + j * 16, aptr + s * BK + j * 4);
            cp16(bdst + st + j * 16, bptr + s * BK + j * 4);
        }
        cp_commit();
    }

    #pragma unroll 1
    for (int c = 0; c < NKT; c++) {
        int st = c % STAGES;
        cp_wait1();            // <=1 group pending -> chunk c's data resident
        __syncthreads();       // orders compute(c-1) before overwrite below

        // issue loads for chunk c+2 into stage (c+2)%STAGES (consumed at c-1)
        if (c + 2 < NKT) {
            int s2 = (c + 2) % STAGES;
            uint32_t stoff = (uint32_t)(s2 * STW) * 4;
            int k0 = (c + 2) * BK;
            #pragma unroll
            for (int j = 0; j < 4; j++) {
                cp16(adst + stoff + j * 16, aptr + k0 + j * 4);
                cp16(bdst + stoff + j * 16, bptr + k0 + j * 4);
            }
        }
        cp_commit();           // uniform group accounting (possibly empty)

        {
            uint32_t abase = sb + (uint32_t)(st * STW) * 4;
            uint32_t bbase = abase + (uint32_t)ABUF * 4;
            #pragma unroll
            for (int k8 = 0; k8 < BK; k8 += 8) {
                uint32_t afr[4][4], bfr[4][2];
                #pragma unroll
                for (int mt = 0; mt < 4; mt++) {
                    int r0 = wm * 64 + mt * 16;
                    uint32_t p0 = abase + ((r0 + g) * SPAD + k8 + tg) * 4;
                    uint32_t p1 = abase + ((r0 + g + 8) * SPAD + k8 + tg) * 4;
                    asm volatile("ld.shared.b32 %0, [%1];" : "=r"(afr[mt][0]) : "r"(p0));
                    asm volatile("ld.shared.b32 %0, [%1];" : "=r"(afr[mt][1]) : "r"(p1));
                    asm volatile("ld.shared.b32 %0, [%1];" : "=r"(afr[mt][2]) : "r"(p0 + 16));
                    asm volatile("ld.shared.b32 %0, [%1];" : "=r"(afr[mt][3]) : "r"(p1 + 16));
                }
                #pragma unroll
                for (int nt = 0; nt < 4; nt++) {
                    int c0 = wn * 32 + nt * 8 + g;
                    uint32_t p = bbase + (c0 * SPAD + k8 + tg) * 4;
                    asm volatile("ld.shared.b32 %0, [%1];" : "=r"(bfr[nt][0]) : "r"(p));
                    asm volatile("ld.shared.b32 %0, [%1];" : "=r"(bfr[nt][1]) : "r"(p + 16));
                    bfr[nt][0] = f2tf_bits(bfr[nt][0]);
                    bfr[nt][1] = f2tf_bits(bfr[nt][1]);
                }
                #pragma unroll
                for (int mt = 0; mt < 4; mt++)
                    #pragma unroll
                    for (int nt = 0; nt < 4; nt++)
                        mma_tf32(acc[mt][nt], afr[mt], bfr[nt]);
            }
        }
    }
    __syncthreads();
}

// kernel 2: act = silu(x@w1^T)*(x@w3^T); B rows interleaved w1/w3 (64 features/block)
__global__ __launch_bounds__(256, 2)
void gemm1_kernel(const float* __restrict__ w1,
                  const float* __restrict__ w3) {
    int e   = blockIdx.z;
    int cnt = g_count[e];
    int m0  = blockIdx.y * BM;
    if (m0 >= cnt) return;
    int f0  = blockIdx.x * (BN / 2);

    extern __shared__ __align__(16) uint32_t smw[];
    uint32_t sb = smem_u32(smw);
    int tid = threadIdx.x, warp = tid >> 5, lane = tid & 31;
    int wm = warp >> 2, wn = warp & 3;     // 2x4 warp grid, 64x32 warp tiles
    int g = lane >> 2, tg = lane & 3;

    int r = tid >> 1, half = (tid & 1) * 16;
    int arow = m0 + r; if (arow >= cnt) arow = cnt - 1;
    int tok = g_tok[e * CAP + arow];
    const float* aptr = g_xtf + (size_t)tok * H_DIM + half;
    const float* bptr = ((r & 1) ? w3 : w1)
                      + ((size_t)e * I_DIM + f0 + (r >> 1)) * H_DIM + half;

    float acc[4][4][4];
    #pragma unroll
    for (int mt = 0; mt < 4; mt++)
        #pragma unroll
        for (int nt = 0; nt < 4; nt++)
            #pragma unroll
            for (int i = 0; i < 4; i++) acc[mt][nt][i] = 0.f;

    gemm_tile<H_DIM / BK>(sb, aptr, bptr, acc, wm, wn, g, tg, tid);

    // epilogue: col 2j=gate, 2j+1=up -> silu(gate)*up, stored tf32-rounded
    #pragma unroll
    for (int mt = 0; mt < 4; mt++) {
        int row = m0 + wm * 64 + mt * 16 + g;
        #pragma unroll
        for (int nt = 0; nt < 4; nt++) {
            int f = f0 + wn * 16 + nt * 4 + tg;
            float* d = acc[mt][nt];
            if (row < cnt) {
                float gt = d[0], up = d[1];
                g_act[((size_t)e * CAP + row) * I_DIM + f] =
                    f2tf_f(gt / (1.f + expf(-gt)) * up);
            }
            if (row + 8 < cnt) {
                float gt = d[2], up = d[3];
                g_act[((size_t)e * CAP + row + 8) * I_DIM + f] =
                    f2tf_f(gt / (1.f + expf(-gt)) * up);
            }
        }
    }
}

// kernel 3: y = act @ w2^T (per-slot output, deterministic)
__global__ __launch_bounds__(256, 2)
void gemm2_kernel(const float* __restrict__ w2) {
    int e   = blockIdx.z;
    int cnt = g_count[e];
    int m0  = blockIdx.y * BM;
    if (m0 >= cnt) return;
    int n0  = blockIdx.x * BN;

    extern __shared__ __align__(16) uint32_t smw[];
    uint32_t sb = smem_u32(smw);
    int tid = threadIdx.x, warp = tid >> 5, lane = tid & 31;
    int wm = warp >> 2, wn = warp & 3;
    int g = lane >> 2, tg = lane & 3;

    int r = tid >> 1, half = (tid & 1) * 16;
    int arow = m0 + r; if (arow >= cnt) arow = cnt - 1;
    const float* aptr = g_act + ((size_t)e * CAP + arow) * I_DIM + half;
    const float* bptr = w2 + ((size_t)e * H_DIM + n0 + r) * I_DIM + half;

    float acc[4][4][4];
    #pragma unroll
    for (int mt = 0; mt < 4; mt++)
        #pragma unroll
        for (int nt = 0; nt < 4; nt++)
            #pragma unroll
            for (int i = 0; i < 4; i++) acc[mt][nt][i] = 0.f;

    gemm_tile<I_DIM / BK>(sb, aptr, bptr, acc, wm, wn, g, tg, tid);

    #pragma unroll
    for (int mt = 0; mt < 4; mt++) {
        int row = m0 + wm * 64 + mt * 16 + g;
        #pragma unroll
        for (int nt = 0; nt < 4; nt++) {
            int col = n0 + wn * 32 + nt * 8 + 2 * tg;
            float* d = acc[mt][nt];
            if (row < cnt)
                *(float2*)&g_y[((size_t)e * CAP + row) * H_DIM + col]
                    = make_float2(d[0], d[1]);
            if (row + 8 < cnt)
                *(float2*)&g_y[((size_t)e * CAP + row + 8) * H_DIM + col]
                    = make_float2(d[2], d[3]);
        }
    }
}

// ---------------- kernel 4: combine ----------------
__global__ __launch_bounds__(256)
void combine_kernel(const float* __restrict__ x, float* __restrict__ out) {
    int t = blockIdx.x;
    __shared__ int   s_n;
    __shared__ float s_zw;
    __shared__ int   s_slot[TOPK];
    __shared__ float s_w[TOPK];
    int tid = threadIdx.x;
    if (tid == 0) { s_n = g_nk[t]; s_zw = g_zero_w[t]; }
    if (tid < TOPK) { s_slot[tid] = g_slots[t * TOPK + tid]; s_w[tid] = g_wts[t * TOPK + tid]; }
    __syncthreads();
    int n = s_n; float zw = s_zw;

    const float* xrow = x + (size_t)t * H_DIM;
    float* orow = out + (size_t)t * H_DIM;
    for (int h = tid * 4; h < H_DIM; h += 256 * 4) {
        float4 xv = *(const float4*)(xrow + h);
        float4 o = make_float4(xv.x * zw, xv.y * zw, xv.z * zw, xv.w * zw);
        for (int k = 0; k < n; k++) {
            const float4 yv = *(const float4*)(g_y + (size_t)s_slot[k] * H_DIM + h);
            float wk = s_w[k];
            o.x += wk * yv.x; o.y += wk * yv.y; o.z += wk * yv.z; o.w += wk * yv.w;
        }
        *(float4*)(orow + h) = o;
    }
}

// ---------------- launcher ----------------
extern "C" void kernel_launch(void* const* d_in, const int* in_sizes, int n_in,
                              void* d_out, int out_size) {
    const float* x    = (const float*)d_in[0];
    const float* rw   = (const float*)d_in[1];
    const float* bias = (const float*)d_in[2];
    const float* w1   = (const float*)d_in[3];
    const float* w3   = (const float*)d_in[4];
    const float* w2   = (const float*)d_in[5];
    float* out = (float*)d_out;

    cudaFuncSetAttribute(gemm1_kernel, cudaFuncAttributeMaxDynamicSharedMemorySize, SMEM_BYTES);
    cudaFuncSetAttribute(gemm2_kernel, cudaFuncAttributeMaxDynamicSharedMemorySize, SMEM_BYTES);

    zero_counts_kernel<<<1, 32>>>();
    round_x_kernel<<<(T_TOK * H_DIM / 4 + 255) / 256, 256>>>(x);
    router_kernel<<<T_TOK, 256>>>(x, rw, bias);
    {
        dim3 g((2 * I_DIM) / BN, T_TOK / BM, E_EXP);  // 16 x 32 x 32
        gemm1_kernel<<<g, 256, SMEM_BYTES>>>(w1, w3);
    }
    {
        dim3 g(H_DIM / BN, T_TOK / BM, E_EXP);        // 16 x 32 x 32
        gemm2_kernel<<<g, 256, SMEM_BYTES>>>(w2);
    }
    combine_kernel<<<T_TOK, 256>>>(x, out);
}

// round 16
// speedup vs baseline: 1.1133x; 1.0912x over previous
#include <cuda_runtime.h>
#include <math.h>
#include <stdint.h>

// ---------------- problem constants ----------------
#define T_TOK 4096
#define H_DIM 2048
#define E_EXP 32
#define NE    48
#define I_DIM 1024
#define TOPK  6
#define ROUTED_SCALE 2.5f
#define CAP   4096
#define RTOK  8            // tokens per router block

// ---------------- device scratch (static, no allocs) ----------------
__device__ int   g_count[E_EXP];
__device__ int   g_tok[E_EXP * CAP];
__device__ int   g_nk[T_TOK];
__device__ int   g_slots[T_TOK * TOPK];
__device__ float g_wts[T_TOK * TOPK];
__device__ float g_zero_w[T_TOK];
__device__ float g_xtf[(size_t)T_TOK * H_DIM];          // x pre-rounded to tf32
__device__ float g_act[(size_t)E_EXP * CAP * I_DIM];    // stored tf32-rounded
__device__ float g_y[(size_t)E_EXP * CAP * H_DIM];

// ---------------- kernel 0 ----------------
__global__ void zero_counts_kernel() {
    int i = threadIdx.x;
    if (i < E_EXP) g_count[i] = 0;
}

// ---------------- helpers ----------------
__device__ __forceinline__ uint32_t f2tf_bits(uint32_t bits) {
    uint32_t r;
    asm("cvt.rna.tf32.f32 %0, %1;" : "=r"(r) : "r"(bits));
    return r;
}
__device__ __forceinline__ float f2tf_f(float f) {
    uint32_t r;
    asm("cvt.rna.tf32.f32 %0, %1;" : "=r"(r) : "f"(f));
    return __uint_as_float(r);
}

// ---------------- kernel 1: batched router ----------------
// 8 tokens per block: router weights (384KB) streamed once per 8 tokens
// instead of once per token. Per-expert dot keeps the EXACT lane-strided
// order + butterfly reduction of the single-token version -> identical bits
// -> identical top-k selection. Also fuses round_x: x rows pass through smem
// and the tf32-rounded copy is written to g_xtf here (router dots use raw x).
__global__ __launch_bounds__(256)
void router_kernel(const float* __restrict__ x,
                   const float* __restrict__ rw,
                   const float* __restrict__ bias) {
    int t0  = blockIdx.x * RTOK;
    int tid = threadIdx.x;
    extern __shared__ float rsm[];
    float* sx   = rsm;                       // [RTOK][H_DIM]
    float* slog = rsm + RTOK * H_DIM;        // [RTOK][NE]

    // load x rows to smem; write tf32-rounded copy to g_xtf
    for (int i = tid * 4; i < RTOK * H_DIM; i += 256 * 4) {
        float4 v = *(const float4*)(x + (size_t)t0 * H_DIM + i);
        *(float4*)(sx + i) = v;
        float4 r = make_float4(f2tf_f(v.x), f2tf_f(v.y), f2tf_f(v.z), f2tf_f(v.w));
        *(float4*)(g_xtf + (size_t)t0 * H_DIM + i) = r;
    }
    __syncthreads();

    int warp = tid >> 5, lane = tid & 31;
    for (int e = warp; e < NE; e += 8) {
        const float* w = rw + (size_t)e * H_DIM;
        float acc[RTOK];
        #pragma unroll
        for (int tk = 0; tk < RTOK; tk++) acc[tk] = 0.f;
        for (int i = lane; i < H_DIM; i += 32) {
            float wv = w[i];
            #pragma unroll
            for (int tk = 0; tk < RTOK; tk++) acc[tk] += sx[tk * H_DIM + i] * wv;
        }
        #pragma unroll
        for (int tk = 0; tk < RTOK; tk++) {
            float a = acc[tk];
            #pragma unroll
            for (int o = 16; o; o >>= 1) a += __shfl_xor_sync(0xffffffffu, a, o);
            if (lane == 0) slog[tk * NE + e] = a;
        }
    }
    __syncthreads();

    if (tid < RTOK) {
        int t = t0 + tid;
        float sc[NE], scc[NE];
        #pragma unroll
        for (int e = 0; e < NE; e++) {
            float s = 1.f / (1.f + expf(-slog[tid * NE + e]));
            sc[e]  = s;
            scc[e] = s + bias[e];
        }
        int ids[TOPK]; float wts[TOPK]; float sum = 0.f;
        bool used[NE];
        #pragma unroll
        for (int e = 0; e < NE; e++) used[e] = false;
        #pragma unroll
        for (int k = 0; k < TOPK; k++) {
            int bi = 0; float bv = -1e30f;
            for (int e = 0; e < NE; e++)
                if (!used[e] && scc[e] > bv) { bv = scc[e]; bi = e; }  // strict > : lowest idx on tie
            used[bi] = true; ids[k] = bi; wts[k] = sc[bi]; sum += sc[bi];
        }
        float inv = ROUTED_SCALE / sum;
        float zw = 0.f;
        int nk = 0;
        #pragma unroll
        for (int k = 0; k < TOPK; k++) {
            float w = wts[k] * inv;
            if (ids[k] >= E_EXP) {
                zw += w;
            } else {
                int e = ids[k];
                int pos = atomicAdd(&g_count[e], 1);
                g_tok[e * CAP + pos] = t;
                g_slots[t * TOPK + nk] = e * CAP + pos;
                g_wts[t * TOPK + nk] = w;
                nk++;
            }
        }
        g_nk[t] = nk;
        g_zero_w[t] = zw;
    }
}
#define RSMEM ((RTOK * H_DIM + RTOK * NE) * 4)

// ---------------- mma + cp.async helpers ----------------
__device__ __forceinline__ void mma_tf32(float* d, const uint32_t* a, const uint32_t* b) {
    asm volatile(
        "mma.sync.aligned.m16n8k8.row.col.f32.tf32.tf32.f32 "
        "{%0,%1,%2,%3}, {%4,%5,%6,%7}, {%8,%9}, {%0,%1,%2,%3};\n"
        : "+f"(d[0]), "+f"(d[1]), "+f"(d[2]), "+f"(d[3])
        : "r"(a[0]), "r"(a[1]), "r"(a[2]), "r"(a[3]),
          "r"(b[0]), "r"(b[1]));
}
__device__ __forceinline__ uint32_t smem_u32(const void* p) {
    uint32_t a;
    asm("{ .reg .u64 t; cvta.to.shared.u64 t, %1; cvt.u32.u64 %0, t; }"
        : "=r"(a) : "l"(p));
    return a;
}
__device__ __forceinline__ void cp16(uint32_t d, const void* s) {
    asm volatile("cp.async.cg.shared.global [%0], [%1], 16;" :: "r"(d), "l"(s));
}
__device__ __forceinline__ void cp_commit() { asm volatile("cp.async.commit_group;" ::: "memory"); }
__device__ __forceinline__ void cp_wait1()  { asm volatile("cp.async.wait_group 1;" ::: "memory"); }

// ---------------- GEMM tiling (R9 config — best measured) ----------------
#define BM 128
#define BN 128
#define BK 16
#define SPAD 20                    // (20g+tg)%32 distinct -> conflict-free frag reads
#define ABUF (BM * SPAD)           // words
#define BBUF (BN * SPAD)
#define STW  (ABUF + BBUF)         // words per stage = 5120
#define STAGES 3
#define SMEM_BYTES (STAGES * STW * 4)   // 61440 B

// Core pipelined tile compute: 8 warps (2x4), 64x32 warp tiles, 256 threads.
// 3 stages, prefetch distance 2, wait_group<=1. A pre-rounded tf32 (no cvt);
// B (weights) cvt'd at the fragment. One barrier per chunk.
template<int NKT>
__device__ __forceinline__ void gemm_tile(uint32_t sb,
                                          const float* aptr,   // row base + half offset
                                          const float* bptr,   // row base + half offset
                                          float acc[4][4][4],
                                          int wm, int wn, int g, int tg,
                                          int tid) {
    uint32_t adst = sb + (uint32_t)((tid >> 1) * SPAD + (tid & 1) * 8) * 4;
    uint32_t bdst = sb + (uint32_t)(ABUF + (tid >> 1) * SPAD + (tid & 1) * 8) * 4;

    // prologue: chunks 0,1 into stages 0,1
    #pragma unroll
    for (int s = 0; s < 2; s++) {
        uint32_t st = (uint32_t)(s * STW) * 4;
        #pragma unroll
        for (int j = 0; j < 2; j++) {
            cp16(adst + st + j * 16, aptr + s * BK + j * 4);
            cp16(bdst + st + j * 16, bptr + s * BK + j * 4);
        }
        cp_commit();
    }

    #pragma unroll 1
    for (int c = 0; c < NKT; c++) {
        int st = c % STAGES;
        cp_wait1();            // chunk c's group complete (<=1 pending)
        __syncthreads();       // orders compute(c-1) before overwrite below

        if (c + 2 < NKT) {
            int s2 = (c + 2) % STAGES;
            uint32_t stoff = (uint32_t)(s2 * STW) * 4;
            int k0 = (c + 2) * BK;
            #pragma unroll
            for (int j = 0; j < 2; j++) {
                cp16(adst + stoff + j * 16, aptr + k0 + j * 4);
                cp16(bdst + stoff + j * 16, bptr + k0 + j * 4);
            }
        }
        cp_commit();           // uniform group accounting

        {
            uint32_t abase = sb + (uint32_t)(st * STW) * 4;
            uint32_t bbase = abase + (uint32_t)ABUF * 4;
            #pragma unroll
            for (int k8 = 0; k8 < BK; k8 += 8) {
                uint32_t afr[4][4], bfr[4][2];
                #pragma unroll
                for (int mt = 0; mt < 4; mt++) {
                    int r0 = wm * 64 + mt * 16;
                    uint32_t p0 = abase + ((r0 + g) * SPAD + k8 + tg) * 4;
                    uint32_t p1 = abase + ((r0 + g + 8) * SPAD + k8 + tg) * 4;
                    asm volatile("ld.shared.b32 %0, [%1];" : "=r"(afr[mt][0]) : "r"(p0));
                    asm volatile("ld.shared.b32 %0, [%1];" : "=r"(afr[mt][1]) : "r"(p1));
                    asm volatile("ld.shared.b32 %0, [%1];" : "=r"(afr[mt][2]) : "r"(p0 + 16));
                    asm volatile("ld.shared.b32 %0, [%1];" : "=r"(afr[mt][3]) : "r"(p1 + 16));
                }
                #pragma unroll
                for (int nt = 0; nt < 4; nt++) {
                    int c0 = wn * 32 + nt * 8 + g;
                    uint32_t p = bbase + (c0 * SPAD + k8 + tg) * 4;
                    asm volatile("ld.shared.b32 %0, [%1];" : "=r"(bfr[nt][0]) : "r"(p));
                    asm volatile("ld.shared.b32 %0, [%1];" : "=r"(bfr[nt][1]) : "r"(p + 16));
                    bfr[nt][0] = f2tf_bits(bfr[nt][0]);
                    bfr[nt][1] = f2tf_bits(bfr[nt][1]);
                }
                #pragma unroll
                for (int mt = 0; mt < 4; mt++)
                    #pragma unroll
                    for (int nt = 0; nt < 4; nt++)
                        mma_tf32(acc[mt][nt], afr[mt], bfr[nt]);
            }
        }
    }
    __syncthreads();
}

// kernel 2: act = silu(x@w1^T)*(x@w3^T); B rows interleaved w1/w3 (64 features/block)
__global__ __launch_bounds__(256, 2)
void gemm1_kernel(const float* __restrict__ w1,
                  const float* __restrict__ w3) {
    int e   = blockIdx.z;
    int cnt = g_count[e];
    int m0  = blockIdx.y * BM;
    if (m0 >= cnt) return;
    int f0  = blockIdx.x * (BN / 2);

    extern __shared__ __align__(16) uint32_t smw[];
    uint32_t sb = smem_u32(smw);
    int tid = threadIdx.x, warp = tid >> 5, lane = tid & 31;
    int wm = warp >> 2, wn = warp & 3;     // 2x4 warp grid, 64x32 warp tiles
    int g = lane >> 2, tg = lane & 3;

    int r = tid >> 1, half = (tid & 1) * 8;
    int arow = m0 + r; if (arow >= cnt) arow = cnt - 1;
    int tok = g_tok[e * CAP + arow];
    const float* aptr = g_xtf + (size_t)tok * H_DIM + half;
    const float* bptr = ((r & 1) ? w3 : w1)
                      + ((size_t)e * I_DIM + f0 + (r >> 1)) * H_DIM + half;

    float acc[4][4][4];
    #pragma unroll
    for (int mt = 0; mt < 4; mt++)
        #pragma unroll
        for (int nt = 0; nt < 4; nt++)
            #pragma unroll
            for (int i = 0; i < 4; i++) acc[mt][nt][i] = 0.f;

    gemm_tile<H_DIM / BK>(sb, aptr, bptr, acc, wm, wn, g, tg, tid);

    // epilogue: col 2j=gate, 2j+1=up -> silu(gate)*up, stored tf32-rounded
    #pragma unroll
    for (int mt = 0; mt < 4; mt++) {
        int row = m0 + wm * 64 + mt * 16 + g;
        #pragma unroll
        for (int nt = 0; nt < 4; nt++) {
            int f = f0 + wn * 16 + nt * 4 + tg;
            float* d = acc[mt][nt];
            if (row < cnt) {
                float gt = d[0], up = d[1];
                g_act[((size_t)e * CAP + row) * I_DIM + f] =
                    f2tf_f(gt / (1.f + expf(-gt)) * up);
            }
            if (row + 8 < cnt) {
                float gt = d[2], up = d[3];
                g_act[((size_t)e * CAP + row + 8) * I_DIM + f] =
                    f2tf_f(gt / (1.f + expf(-gt)) * up);
            }
        }
    }
}

// kernel 3: y = act @ w2^T (per-slot output, deterministic)
__global__ __launch_bounds__(256, 2)
void gemm2_kernel(const float* __restrict__ w2) {
    int e   = blockIdx.z;
    int cnt = g_count[e];
    int m0  = blockIdx.y * BM;
    if (m0 >= cnt) return;
    int n0  = blockIdx.x * BN;

    extern __shared__ __align__(16) uint32_t smw[];
    uint32_t sb = smem_u32(smw);
    int tid = threadIdx.x, warp = tid >> 5, lane = tid & 31;
    int wm = warp >> 2, wn = warp & 3;
    int g = lane >> 2, tg = lane & 3;

    int r = tid >> 1, half = (tid & 1) * 8;
    int arow = m0 + r; if (arow >= cnt) arow = cnt - 1;
    const float* aptr = g_act + ((size_t)e * CAP + arow) * I_DIM + half;
    const float* bptr = w2 + ((size_t)e * H_DIM + n0 + r) * I_DIM + half;

    float acc[4][4][4];
    #pragma unroll
    for (int mt = 0; mt < 4; mt++)
        #pragma unroll
        for (int nt = 0; nt < 4; nt++)
            #pragma unroll
            for (int i = 0; i < 4; i++) acc[mt][nt][i] = 0.f;

    gemm_tile<I_DIM / BK>(sb, aptr, bptr, acc, wm, wn, g, tg, tid);

    #pragma unroll
    for (int mt = 0; mt < 4; mt++) {
        int row = m0 + wm * 64 + mt * 16 + g;
        #pragma unroll
        for (int nt = 0; nt < 4; nt++) {
            int col = n0 + wn * 32 + nt * 8 + 2 * tg;
            float* d = acc[mt][nt];
            if (row < cnt)
                *(float2*)&g_y[((size_t)e * CAP + row) * H_DIM + col]
                    = make_float2(d[0], d[1]);
            if (row + 8 < cnt)
                *(float2*)&g_y[((size_t)e * CAP + row + 8) * H_DIM + col]
                    = make_float2(d[2], d[3]);
        }
    }
}

// ---------------- kernel 4: combine ----------------
__global__ __launch_bounds__(256)
void combine_kernel(const float* __restrict__ x, float* __restrict__ out) {
    int t = blockIdx.x;
    __shared__ int   s_n;
    __shared__ float s_zw;
    __shared__ int   s_slot[TOPK];
    __shared__ float s_w[TOPK];
    int tid = threadIdx.x;
    if (tid == 0) { s_n = g_nk[t]; s_zw = g_zero_w[t]; }
    if (tid < TOPK) { s_slot[tid] = g_slots[t * TOPK + tid]; s_w[tid] = g_wts[t * TOPK + tid]; }
    __syncthreads();
    int n = s_n; float zw = s_zw;

    const float* xrow = x + (size_t)t * H_DIM;
    float* orow = out + (size_t)t * H_DIM;
    for (int h = tid * 4; h < H_DIM; h += 256 * 4) {
        float4 xv = *(const float4*)(xrow + h);
        float4 o = make_float4(xv.x * zw, xv.y * zw, xv.z * zw, xv.w * zw);
        for (int k = 0; k < n; k++) {
            const float4 yv = *(const float4*)(g_y + (size_t)s_slot[k] * H_DIM + h);
            float wk = s_w[k];
            o.x += wk * yv.x; o.y += wk * yv.y; o.z += wk * yv.z; o.w += wk * yv.w;
        }
        *(float4*)(orow + h) = o;
    }
}

// ---------------- launcher ----------------
extern "C" void kernel_launch(void* const* d_in, const int* in_sizes, int n_in,
                              void* d_out, int out_size) {
    const float* x    = (const float*)d_in[0];
    const float* rw   = (const float*)d_in[1];
    const float* bias = (const float*)d_in[2];
    const float* w1   = (const float*)d_in[3];
    const float* w3   = (const float*)d_in[4];
    const float* w2   = (const float*)d_in[5];
    float* out = (float*)d_out;

    cudaFuncSetAttribute(router_kernel, cudaFuncAttributeMaxDynamicSharedMemorySize, RSMEM);
    cudaFuncSetAttribute(gemm1_kernel, cudaFuncAttributeMaxDynamicSharedMemorySize, SMEM_BYTES);
    cudaFuncSetAttribute(gemm2_kernel, cudaFuncAttributeMaxDynamicSharedMemorySize, SMEM_BYTES);

    zero_counts_kernel<<<1, 32>>>();
    router_kernel<<<T_TOK / RTOK, 256, RSMEM>>>(x, rw, bias);
    {
        dim3 g((2 * I_DIM) / BN, T_TOK / BM, E_EXP);  // 16 x 32 x 32
        gemm1_kernel<<<g, 256, SMEM_BYTES>>>(w1, w3);
    }
    {
        dim3 g(H_DIM / BN, T_TOK / BM, E_EXP);        // 16 x 32 x 32
        gemm2_kernel<<<g, 256, SMEM_BYTES>>>(w2);
    }
    combine_kernel<<<T_TOK, 256>>>(x, out);
}